// round 1
// baseline (speedup 1.0000x reference)
#include <cuda_runtime.h>
#include <math.h>

#define NN 50000
#define IN_DIM 512
#define HIDD 256
#define HEADS 8
#define HC 32
#define EDGES 600000
#define KK 4
#define LN_EPS 1e-5f

// ---------------- scratch (static device globals; no allocation) ----------------
__device__ float g_h0[NN * HIDD];            // 51.2 MB
__device__ float g_h1[NN * HIDD];            // 51.2 MB
__device__ float g_outs[KK * NN * HIDD];     // 204.8 MB
__device__ float g_dinv[NN];
__device__ float g_as[NN * HEADS];
__device__ float g_ad[NN * HEADS];
__device__ float g_m[NN * HEADS];
__device__ float g_ssum[NN * HEADS];
__device__ float g_w[NN * KK];

// ---------------- helpers ----------------
__device__ __forceinline__ float lrelu(float x) { return x > 0.f ? x : 0.2f * x; }

__device__ __forceinline__ void atomicMaxFloat(float* addr, float value) {
    int* ai = (int*)addr;
    int old = *ai;
    while (__int_as_float(old) < value) {
        int assumed = old;
        old = atomicCAS(ai, assumed, __float_as_int(value));
        if (old == assumed) break;
    }
}

static inline int cdiv(int a, int b) { return (a + b - 1) / b; }

// ---------------- elementwise ----------------
__global__ void fill_kernel(float* p, float v, int n) {
    int i = blockIdx.x * blockDim.x + threadIdx.x;
    if (i < n) p[i] = v;
}

__global__ void deg_count_kernel(const int* __restrict__ dst, float* __restrict__ deg, int e) {
    int i = blockIdx.x * blockDim.x + threadIdx.x;
    if (i < e) atomicAdd(&deg[dst[i]], 1.0f);
}

__global__ void rsqrt_kernel(float* p, int n) {
    int i = blockIdx.x * blockDim.x + threadIdx.x;
    if (i < n) p[i] = rsqrtf(p[i]);
}

__global__ void relu_kernel(float* p, int n) {
    int i = blockIdx.x * blockDim.x + threadIdx.x;
    if (i < n) p[i] = fmaxf(p[i], 0.0f);
}

__global__ void tanh_bias_kernel(float* __restrict__ t, const float* __restrict__ b) {
    int idx = blockIdx.x * 256 + threadIdx.x;   // grid = NN blocks
    int c = idx & (HIDD - 1);
    t[idx] = tanhf(t[idx] + b[c]);
}

// ---------------- GEMM: C[M,Nc] = A[M,Kd] @ B[Kd,Nc]  (optional accumulate) ----------------
__global__ void gemm64_kernel(const float* __restrict__ A, const float* __restrict__ B,
                              float* __restrict__ C, int M, int Kd, int Nc, int accum) {
    __shared__ float As[16][68];
    __shared__ float Bs[16][68];
    int tx = threadIdx.x, ty = threadIdx.y;
    int tid = ty * 16 + tx;
    int rowBase = blockIdx.y * 64;
    int colBase = blockIdx.x * 64;

    int la_r = tid >> 2;          // 0..63
    int la_k = (tid & 3) * 4;     // 0,4,8,12
    int lb_k = tid >> 4;          // 0..15
    int lb_n = (tid & 15) * 4;    // 0..60

    float acc[4][4];
#pragma unroll
    for (int i = 0; i < 4; i++)
#pragma unroll
        for (int j = 0; j < 4; j++) acc[i][j] = 0.f;

    for (int k0 = 0; k0 < Kd; k0 += 16) {
        int ar = rowBase + la_r;
        float4 av = make_float4(0.f, 0.f, 0.f, 0.f);
        if (ar < M) av = *(const float4*)(A + (size_t)ar * Kd + k0 + la_k);
        As[la_k + 0][la_r] = av.x;
        As[la_k + 1][la_r] = av.y;
        As[la_k + 2][la_r] = av.z;
        As[la_k + 3][la_r] = av.w;

        float4 bv = *(const float4*)(B + (size_t)(k0 + lb_k) * Nc + colBase + lb_n);
        Bs[lb_k][lb_n + 0] = bv.x;
        Bs[lb_k][lb_n + 1] = bv.y;
        Bs[lb_k][lb_n + 2] = bv.z;
        Bs[lb_k][lb_n + 3] = bv.w;
        __syncthreads();

#pragma unroll
        for (int kk = 0; kk < 16; kk++) {
            float a0 = As[kk][ty * 4 + 0];
            float a1 = As[kk][ty * 4 + 1];
            float a2 = As[kk][ty * 4 + 2];
            float a3 = As[kk][ty * 4 + 3];
            float b0 = Bs[kk][tx * 4 + 0];
            float b1 = Bs[kk][tx * 4 + 1];
            float b2 = Bs[kk][tx * 4 + 2];
            float b3 = Bs[kk][tx * 4 + 3];
            acc[0][0] += a0 * b0; acc[0][1] += a0 * b1; acc[0][2] += a0 * b2; acc[0][3] += a0 * b3;
            acc[1][0] += a1 * b0; acc[1][1] += a1 * b1; acc[1][2] += a1 * b2; acc[1][3] += a1 * b3;
            acc[2][0] += a2 * b0; acc[2][1] += a2 * b1; acc[2][2] += a2 * b2; acc[2][3] += a2 * b3;
            acc[3][0] += a3 * b0; acc[3][1] += a3 * b1; acc[3][2] += a3 * b2; acc[3][3] += a3 * b3;
        }
        __syncthreads();
    }

#pragma unroll
    for (int i = 0; i < 4; i++) {
        int r = rowBase + ty * 4 + i;
        if (r >= M) continue;
        float* cp = C + (size_t)r * Nc + colBase + tx * 4;
        float4 v = make_float4(acc[i][0], acc[i][1], acc[i][2], acc[i][3]);
        if (accum) {
            float4 old = *(float4*)cp;
            v.x += old.x; v.y += old.y; v.z += old.z; v.w += old.w;
        }
        *(float4*)cp = v;
    }
}

// ---------------- GCN ----------------
// out[n,c] = h[n,c]*dinv[n]^2 + bias[c]   (self-loop term + bias)
__global__ void gcn_init_kernel(const float* __restrict__ h, const float* __restrict__ dinv,
                                const float* __restrict__ bias, float* __restrict__ out) {
    int idx = blockIdx.x * 256 + threadIdx.x;  // grid = NN blocks
    int n = idx >> 8, c = idx & 255;
    float di = dinv[n];
    out[idx] = h[idx] * di * di + bias[c];
}

// one block per edge, thread = column
__global__ void gcn_scatter_kernel(const float* __restrict__ h, const int* __restrict__ src,
                                   const int* __restrict__ dst, const float* __restrict__ dinv,
                                   float* __restrict__ out) {
    int e = blockIdx.x;
    __shared__ int ss, dd;
    __shared__ float coef;
    if (threadIdx.x == 0) {
        ss = src[e];
        dd = dst[e];
        coef = dinv[ss] * dinv[dd];
    }
    __syncthreads();
    int c = threadIdx.x;
    atomicAdd(&out[(size_t)dd * HIDD + c], h[(size_t)ss * HIDD + c] * coef);
}

// ---------------- GAT ----------------
// block = node, warp = head: per-node head scores
__global__ void gat_asad_kernel(const float* __restrict__ hg, const float* __restrict__ asrc,
                                const float* __restrict__ adst, float* __restrict__ as_,
                                float* __restrict__ ad_) {
    int n = blockIdx.x;
    int h = threadIdx.x >> 5, c = threadIdx.x & 31;
    float v = hg[(size_t)n * HIDD + h * HC + c];
    float s = v * asrc[h * HC + c];
    float d = v * adst[h * HC + c];
#pragma unroll
    for (int o = 16; o; o >>= 1) {
        s += __shfl_down_sync(0xffffffffu, s, o);
        d += __shfl_down_sync(0xffffffffu, d, o);
    }
    if (c == 0) {
        as_[n * HEADS + h] = s;
        ad_[n * HEADS + h] = d;
    }
}

__global__ void gat_minit_kernel(const float* __restrict__ as_, const float* __restrict__ ad_,
                                 float* __restrict__ m) {
    int i = blockIdx.x * blockDim.x + threadIdx.x;
    if (i < NN * HEADS) m[i] = lrelu(as_[i] + ad_[i]);
}

__global__ void gat_mmax_kernel(const int* __restrict__ src, const int* __restrict__ dst,
                                const float* __restrict__ as_, const float* __restrict__ ad_,
                                float* __restrict__ m) {
    int i = blockIdx.x * blockDim.x + threadIdx.x;
    if (i >= EDGES * HEADS) return;
    int e = i >> 3, h = i & 7;
    int s = src[e], d = dst[e];
    float ev = lrelu(as_[s * HEADS + h] + ad_[d * HEADS + h]);
    atomicMaxFloat(&m[d * HEADS + h], ev);
}

__global__ void gat_ssum_init_kernel(const float* __restrict__ as_, const float* __restrict__ ad_,
                                     const float* __restrict__ m, float* __restrict__ ssum) {
    int i = blockIdx.x * blockDim.x + threadIdx.x;
    if (i < NN * HEADS) ssum[i] = expf(lrelu(as_[i] + ad_[i]) - m[i]);
}

__global__ void gat_ssum_add_kernel(const int* __restrict__ src, const int* __restrict__ dst,
                                    const float* __restrict__ as_, const float* __restrict__ ad_,
                                    const float* __restrict__ m, float* __restrict__ ssum) {
    int i = blockIdx.x * blockDim.x + threadIdx.x;
    if (i >= EDGES * HEADS) return;
    int e = i >> 3, h = i & 7;
    int s = src[e], d = dst[e];
    float ev = lrelu(as_[s * HEADS + h] + ad_[d * HEADS + h]);
    atomicAdd(&ssum[d * HEADS + h], expf(ev - m[d * HEADS + h]));
}

// self-loop contribution + bias
__global__ void gat_out_init_kernel(const float* __restrict__ hg, const float* __restrict__ as_,
                                    const float* __restrict__ ad_, const float* __restrict__ m,
                                    const float* __restrict__ ssum, const float* __restrict__ bias,
                                    float* __restrict__ out) {
    int idx = blockIdx.x * 256 + threadIdx.x;  // grid = NN blocks
    int n = idx >> 8, c = idx & 255;
    int h = c >> 5;
    int nh = n * HEADS + h;
    float alpha = expf(lrelu(as_[nh] + ad_[nh]) - m[nh]) / ssum[nh];
    out[idx] = hg[idx] * alpha + bias[c];
}

// block = edge, warp = head, lane = channel
__global__ void gat_scatter_kernel(const float* __restrict__ hg, const int* __restrict__ src,
                                   const int* __restrict__ dst, const float* __restrict__ as_,
                                   const float* __restrict__ ad_, const float* __restrict__ m,
                                   const float* __restrict__ ssum, float* __restrict__ out) {
    int e = blockIdx.x;
    __shared__ int ss, dd;
    if (threadIdx.x == 0) {
        ss = src[e];
        dd = dst[e];
    }
    __syncthreads();
    int h = threadIdx.x >> 5, c = threadIdx.x & 31;
    int s = ss, d = dd;
    float alpha = 0.f;
    if (c == 0) {
        int snh = s * HEADS + h, dnh = d * HEADS + h;
        float ev = lrelu(as_[snh] + ad_[dnh]);
        alpha = expf(ev - m[dnh]) / ssum[dnh];
    }
    alpha = __shfl_sync(0xffffffffu, alpha, 0);
    atomicAdd(&out[(size_t)d * HIDD + h * HC + c], hg[(size_t)s * HIDD + h * HC + c] * alpha);
}

// ---------------- LayerNorm (block per node) ----------------
__global__ void ln_kernel(const float* __restrict__ h, const float* __restrict__ g,
                          const float* __restrict__ b, float* __restrict__ out) {
    int n = blockIdx.x, c = threadIdx.x;
    float v = h[(size_t)n * HIDD + c];
    __shared__ float red[8];
    __shared__ float s_mu, s_rstd;

    float s = v;
#pragma unroll
    for (int o = 16; o; o >>= 1) s += __shfl_down_sync(0xffffffffu, s, o);
    if ((c & 31) == 0) red[c >> 5] = s;
    __syncthreads();
    if (c == 0) {
        float t = 0.f;
#pragma unroll
        for (int i = 0; i < 8; i++) t += red[i];
        s_mu = t * (1.0f / HIDD);
    }
    __syncthreads();
    float dv = v - s_mu;
    float q = dv * dv;
#pragma unroll
    for (int o = 16; o; o >>= 1) q += __shfl_down_sync(0xffffffffu, q, o);
    if ((c & 31) == 0) red[c >> 5] = q;
    __syncthreads();
    if (c == 0) {
        float t = 0.f;
#pragma unroll
        for (int i = 0; i < 8; i++) t += red[i];
        s_rstd = rsqrtf(t * (1.0f / HIDD) + LN_EPS);
    }
    __syncthreads();
    out[(size_t)n * HIDD + c] = dv * s_rstd * g[c] + b[c];
}

// ---------------- fusion ----------------
// warp per node: logits = t @ fW2 + fb2, softmax over K=4
__global__ void fuse_logits_kernel(const float* __restrict__ t, const float* __restrict__ W2,
                                   const float* __restrict__ b2, float* __restrict__ w) {
    int gw = (blockIdx.x * blockDim.x + threadIdx.x) >> 5;
    int lane = threadIdx.x & 31;
    if (gw >= NN) return;
    const float* row = t + (size_t)gw * HIDD;
    float a0 = 0.f, a1 = 0.f, a2 = 0.f, a3 = 0.f;
    for (int c = lane; c < HIDD; c += 32) {
        float tv = row[c];
        a0 += tv * W2[c * 4 + 0];
        a1 += tv * W2[c * 4 + 1];
        a2 += tv * W2[c * 4 + 2];
        a3 += tv * W2[c * 4 + 3];
    }
#pragma unroll
    for (int o = 16; o; o >>= 1) {
        a0 += __shfl_down_sync(0xffffffffu, a0, o);
        a1 += __shfl_down_sync(0xffffffffu, a1, o);
        a2 += __shfl_down_sync(0xffffffffu, a2, o);
        a3 += __shfl_down_sync(0xffffffffu, a3, o);
    }
    if (lane == 0) {
        float l0 = a0 + b2[0], l1 = a1 + b2[1], l2 = a2 + b2[2], l3 = a3 + b2[3];
        float mx = fmaxf(fmaxf(l0, l1), fmaxf(l2, l3));
        float e0 = expf(l0 - mx), e1 = expf(l1 - mx), e2 = expf(l2 - mx), e3 = expf(l3 - mx);
        float inv = 1.0f / (e0 + e1 + e2 + e3);
        w[gw * 4 + 0] = e0 * inv;
        w[gw * 4 + 1] = e1 * inv;
        w[gw * 4 + 2] = e2 * inv;
        w[gw * 4 + 3] = e3 * inv;
    }
}

__global__ void combine_kernel(const float* __restrict__ w, float* __restrict__ out) {
    int idx = blockIdx.x * 256 + threadIdx.x;  // grid = NN blocks
    int n = idx >> 8;
    float acc = 0.f;
#pragma unroll
    for (int k = 0; k < KK; k++) acc += w[n * KK + k] * g_outs[(size_t)k * NN * HIDD + idx];
    out[idx] = acc;
}

// ---------------- host ----------------
extern "C" void kernel_launch(void* const* d_in, const int* in_sizes, int n_in,
                              void* d_out, int out_size) {
    // resolve input ordering: setup_inputs dict order vs reference signature order
    const float *x, *style, *stress;
    const int* ei[KK];
    int base;
    if (in_sizes[1] == 2 * EDGES) {
        // signature order: x, ei0..ei3, style, stress, weights...
        x = (const float*)d_in[0];
        for (int k = 0; k < KK; k++) ei[k] = (const int*)d_in[1 + k];
        style = (const float*)d_in[5];
        stress = (const float*)d_in[6];
        base = 7;
    } else {
        // setup_inputs order: x, style, stress, ei0..ei3, weights...
        x = (const float*)d_in[0];
        style = (const float*)d_in[1];
        stress = (const float*)d_in[2];
        for (int k = 0; k < KK; k++) ei[k] = (const int*)d_in[3 + k];
        base = 7;
    }
    const float* gW0 = (const float*)d_in[base + 0];
    const float* gb0 = (const float*)d_in[base + 1];
    const float* gW1 = (const float*)d_in[base + 2];
    const float* gb1 = (const float*)d_in[base + 3];
    const float* gW2 = (const float*)d_in[base + 4];
    const float* gb2 = (const float*)d_in[base + 5];
    const float* aW  = (const float*)d_in[base + 6];
    const float* aas = (const float*)d_in[base + 7];
    const float* aad = (const float*)d_in[base + 8];
    const float* ab  = (const float*)d_in[base + 9];
    const float* lg  = (const float*)d_in[base + 10];
    const float* lb  = (const float*)d_in[base + 11];
    const float* fW1 = (const float*)d_in[base + 12];
    const float* fb1 = (const float*)d_in[base + 13];
    const float* fW2 = (const float*)d_in[base + 14];
    const float* fb2 = (const float*)d_in[base + 15];

    float *h0, *h1, *outs, *dinv, *as_, *ad_, *m_, *ssum_, *wbuf;
    cudaGetSymbolAddress((void**)&h0, g_h0);
    cudaGetSymbolAddress((void**)&h1, g_h1);
    cudaGetSymbolAddress((void**)&outs, g_outs);
    cudaGetSymbolAddress((void**)&dinv, g_dinv);
    cudaGetSymbolAddress((void**)&as_, g_as);
    cudaGetSymbolAddress((void**)&ad_, g_ad);
    cudaGetSymbolAddress((void**)&m_, g_m);
    cudaGetSymbolAddress((void**)&ssum_, g_ssum);
    cudaGetSymbolAddress((void**)&wbuf, g_w);

    dim3 gblk(16, 16);
    const int NH = NN * HIDD;

    for (int k = 0; k < KK; k++) {
        const int* src = ei[k];
        const int* dst = ei[k] + EDGES;

        // symmetric-norm degree (with self-loop)
        fill_kernel<<<cdiv(NN, 256), 256>>>(dinv, 1.0f, NN);
        deg_count_kernel<<<cdiv(EDGES, 256), 256>>>(dst, dinv, EDGES);
        rsqrt_kernel<<<cdiv(NN, 256), 256>>>(dinv, NN);

        // GCN layer 0: x[N,512] @ W0 -> h1; propagate -> h0; relu
        gemm64_kernel<<<dim3(HIDD / 64, cdiv(NN, 64)), gblk>>>(x, gW0 + (size_t)k * IN_DIM * HIDD,
                                                               h1, NN, IN_DIM, HIDD, 0);
        gcn_init_kernel<<<NN, 256>>>(h1, dinv, gb0 + k * HIDD, h0);
        gcn_scatter_kernel<<<EDGES, 256>>>(h1, src, dst, dinv, h0);
        relu_kernel<<<cdiv(NH, 256), 256>>>(h0, NH);

        // GCN layer 1
        gemm64_kernel<<<dim3(HIDD / 64, cdiv(NN, 64)), gblk>>>(h0, gW1 + (size_t)k * HIDD * HIDD,
                                                               h1, NN, HIDD, HIDD, 0);
        gcn_init_kernel<<<NN, 256>>>(h1, dinv, gb1 + k * HIDD, h0);
        gcn_scatter_kernel<<<EDGES, 256>>>(h1, src, dst, dinv, h0);
        relu_kernel<<<cdiv(NH, 256), 256>>>(h0, NH);

        // GCN layer 2
        gemm64_kernel<<<dim3(HIDD / 64, cdiv(NN, 64)), gblk>>>(h0, gW2 + (size_t)k * HIDD * HIDD,
                                                               h1, NN, HIDD, HIDD, 0);
        gcn_init_kernel<<<NN, 256>>>(h1, dinv, gb2 + k * HIDD, h0);
        gcn_scatter_kernel<<<EDGES, 256>>>(h1, src, dst, dinv, h0);
        relu_kernel<<<cdiv(NH, 256), 256>>>(h0, NH);

        // GAT
        gemm64_kernel<<<dim3(HIDD / 64, cdiv(NN, 64)), gblk>>>(h0, aW + (size_t)k * HIDD * HIDD,
                                                               h1, NN, HIDD, HIDD, 0);
        gat_asad_kernel<<<NN, 256>>>(h1, aas + k * HEADS * HC, aad + k * HEADS * HC, as_, ad_);
        gat_minit_kernel<<<cdiv(NN * HEADS, 256), 256>>>(as_, ad_, m_);
        gat_mmax_kernel<<<cdiv(EDGES * HEADS, 256), 256>>>(src, dst, as_, ad_, m_);
        gat_ssum_init_kernel<<<cdiv(NN * HEADS, 256), 256>>>(as_, ad_, m_, ssum_);
        gat_ssum_add_kernel<<<cdiv(EDGES * HEADS, 256), 256>>>(src, dst, as_, ad_, m_, ssum_);
        gat_out_init_kernel<<<NN, 256>>>(h1, as_, ad_, m_, ssum_, ab + k * HIDD, h0);
        gat_scatter_kernel<<<EDGES, 256>>>(h1, src, dst, as_, ad_, m_, ssum_, h0);

        // LayerNorm -> outs[k]
        ln_kernel<<<NN, 256>>>(h0, lg + k * HIDD, lb + k * HIDD, outs + (size_t)k * NN * HIDD);
    }

    // fusion: t = tanh([style,stress] @ fW1 + fb1)
    gemm64_kernel<<<dim3(HIDD / 64, cdiv(NN, 64)), gblk>>>(style, fW1, h1, NN, HIDD, HIDD, 0);
    gemm64_kernel<<<dim3(HIDD / 64, cdiv(NN, 64)), gblk>>>(stress, fW1 + (size_t)HIDD * HIDD, h1,
                                                           NN, HIDD, HIDD, 1);
    tanh_bias_kernel<<<NN, 256>>>(h1, fb1);
    fuse_logits_kernel<<<cdiv(NN * 32, 256), 256>>>(h1, fW2, fb2, wbuf);
    combine_kernel<<<NN, 256>>>(wbuf, (float*)d_out);
}

// round 3
// speedup vs baseline: 2.0488x; 2.0488x over previous
#include <cuda_runtime.h>
#include <math.h>

#define NN 50000
#define IN_DIM 512
#define HIDD 256
#define HEADS 8
#define HC 32
#define EDGES 600000
#define KK 4
#define LN_EPS 1e-5f

// ---------------- scratch (static device globals; no allocation) ----------------
__device__ float g_h0[NN * HIDD];            // 51.2 MB
__device__ float g_h1[NN * HIDD];            // 51.2 MB
__device__ float g_h2[NN * HIDD];            // 51.2 MB
__device__ float g_h3[NN * HIDD];            // 51.2 MB
__device__ float g_outs[KK * NN * HIDD];     // 204.8 MB
__device__ float g_dinv[NN];
__device__ float g_as[NN * HEADS];
__device__ float g_ad[NN * HEADS];
__device__ float g_m[NN * HEADS];
__device__ float g_ssum[NN * HEADS];
__device__ float g_w[NN * KK];

__device__ __forceinline__ float lrelu(float x) { return x > 0.f ? x : 0.2f * x; }

__device__ __forceinline__ void atomicMaxFloat(float* addr, float value) {
    int* ai = (int*)addr;
    int old = *ai;
    while (__int_as_float(old) < value) {
        int assumed = old;
        old = atomicCAS(ai, assumed, __float_as_int(value));
        if (old == assumed) break;
    }
}

static inline int cdiv(int a, int b) { return (a + b - 1) / b; }

// ---------------- elementwise ----------------
__global__ void fill_kernel(float* p, float v, int n) {
    int i = blockIdx.x * blockDim.x + threadIdx.x;
    if (i < n) p[i] = v;
}

__global__ void deg_count_kernel(const int* __restrict__ dst, float* __restrict__ deg, int e) {
    int i = blockIdx.x * blockDim.x + threadIdx.x;
    if (i < e) atomicAdd(&deg[dst[i]], 1.0f);
}

__global__ void rsqrt_kernel(float* p, int n) {
    int i = blockIdx.x * blockDim.x + threadIdx.x;
    if (i < n) p[i] = rsqrtf(p[i]);
}

__global__ void tanh_bias_kernel(float* __restrict__ t, const float* __restrict__ b) {
    int idx = blockIdx.x * 256 + threadIdx.x;   // grid = NN blocks
    int c = idx & (HIDD - 1);
    t[idx] = tanhf(t[idx] + b[c]);
}

// ---------------- GEMM: C[M,Nc] = op(A)[M,Kd] @ B[Kd,Nc] ----------------
// flags: bit0 = accumulate into C, bit1 = relu(A) on load
// If out2 != nullptr: also write out2[r,c] = C[r,c]*dinv[r]^2 + bias[c]
// NOTE: out2 must NOT alias A (blocks read A while others write out2).
#define TM 128
#define TN 128
#define TK 16

__global__ __launch_bounds__(256, 2)
void gemm128_kernel(const float* __restrict__ A, const float* __restrict__ B,
                    float* __restrict__ C, int M, int Kd, int Nc, int flags,
                    float* __restrict__ out2, const float* __restrict__ dinv,
                    const float* __restrict__ bias) {
    __shared__ float As[TK][TM + 4];
    __shared__ float Bs[TK][TN + 4];

    const int tid = threadIdx.x;
    const int tx = tid & 15, ty = tid >> 4;
    const int rowBase = blockIdx.y * TM;
    const int colBase = blockIdx.x * TN;
    const bool doRelu = (flags & 2) != 0;

    float acc[8][8];
#pragma unroll
    for (int i = 0; i < 8; i++)
#pragma unroll
        for (int j = 0; j < 8; j++) acc[i][j] = 0.f;

    for (int k0 = 0; k0 < Kd; k0 += TK) {
#pragma unroll
        for (int i = 0; i < 2; i++) {
            int idx = tid + i * 256;
            // A tile: 128 rows x 16 k, float4 along k
            int r = idx >> 2, kq = (idx & 3) * 4;
            float4 av = make_float4(0.f, 0.f, 0.f, 0.f);
            if (rowBase + r < M)
                av = *(const float4*)(A + (size_t)(rowBase + r) * Kd + k0 + kq);
            if (doRelu) {
                av.x = fmaxf(av.x, 0.f); av.y = fmaxf(av.y, 0.f);
                av.z = fmaxf(av.z, 0.f); av.w = fmaxf(av.w, 0.f);
            }
            As[kq + 0][r] = av.x;
            As[kq + 1][r] = av.y;
            As[kq + 2][r] = av.z;
            As[kq + 3][r] = av.w;
            // B tile: 16 k x 128 n, float4 along n
            int kb = idx >> 5, nb = (idx & 31) * 4;
            float4 bv = *(const float4*)(B + (size_t)(k0 + kb) * Nc + colBase + nb);
            *(float4*)&Bs[kb][nb] = bv;
        }
        __syncthreads();

#pragma unroll
        for (int kk = 0; kk < TK; kk++) {
            float a[8], b[8];
            *(float4*)(a)     = *(const float4*)&As[kk][ty * 4];
            *(float4*)(a + 4) = *(const float4*)&As[kk][ty * 4 + 64];
            *(float4*)(b)     = *(const float4*)&Bs[kk][tx * 4];
            *(float4*)(b + 4) = *(const float4*)&Bs[kk][tx * 4 + 64];
#pragma unroll
            for (int i = 0; i < 8; i++)
#pragma unroll
                for (int j = 0; j < 8; j++) acc[i][j] += a[i] * b[j];
        }
        __syncthreads();
    }

    const bool accum = (flags & 1) != 0;
#pragma unroll
    for (int i = 0; i < 8; i++) {
        int r = rowBase + ty * 4 + (i & 3) + (i >> 2) * 64;
        if (r >= M) continue;
        float di2 = 0.f;
        if (out2) { float di = dinv[r]; di2 = di * di; }
#pragma unroll
        for (int jh = 0; jh < 2; jh++) {
            int cCol = colBase + tx * 4 + jh * 64;
            float4 v = make_float4(acc[i][jh * 4 + 0], acc[i][jh * 4 + 1],
                                   acc[i][jh * 4 + 2], acc[i][jh * 4 + 3]);
            float* cp = C + (size_t)r * Nc + cCol;
            if (accum) {
                float4 old = *(float4*)cp;
                v.x += old.x; v.y += old.y; v.z += old.z; v.w += old.w;
            }
            *(float4*)cp = v;
            if (out2) {
                float4 w;
                w.x = v.x * di2 + bias[cCol + 0];
                w.y = v.y * di2 + bias[cCol + 1];
                w.z = v.z * di2 + bias[cCol + 2];
                w.w = v.w * di2 + bias[cCol + 3];
                *(float4*)(out2 + (size_t)r * Nc + cCol) = w;
            }
        }
    }
}

// ---------------- GCN scatter: 64 threads per edge, float4 ----------------
__global__ void gcn_scatter_kernel(const float* __restrict__ h, const int* __restrict__ src,
                                   const int* __restrict__ dst, const float* __restrict__ dinv,
                                   float* __restrict__ out) {
    unsigned gid = blockIdx.x * 256 + threadIdx.x;
    int e = gid >> 6;
    int t = gid & 63;
    if (e >= EDGES) return;
    int s = __ldg(&src[e]);
    int d = __ldg(&dst[e]);
    float coef = __ldg(&dinv[s]) * __ldg(&dinv[d]);
    float4 v = *(const float4*)(h + (size_t)s * HIDD + t * 4);
    float* o = out + (size_t)d * HIDD + t * 4;
    atomicAdd(o + 0, v.x * coef);
    atomicAdd(o + 1, v.y * coef);
    atomicAdd(o + 2, v.z * coef);
    atomicAdd(o + 3, v.w * coef);
}

// ---------------- GAT ----------------
__global__ void gat_asad_kernel(const float* __restrict__ hg, const float* __restrict__ asrc,
                                const float* __restrict__ adst, float* __restrict__ as_,
                                float* __restrict__ ad_) {
    int n = blockIdx.x;
    int h = threadIdx.x >> 5, c = threadIdx.x & 31;
    float v = hg[(size_t)n * HIDD + h * HC + c];
    float s = v * asrc[h * HC + c];
    float d = v * adst[h * HC + c];
#pragma unroll
    for (int o = 16; o; o >>= 1) {
        s += __shfl_down_sync(0xffffffffu, s, o);
        d += __shfl_down_sync(0xffffffffu, d, o);
    }
    if (c == 0) {
        as_[n * HEADS + h] = s;
        ad_[n * HEADS + h] = d;
    }
}

__global__ void gat_minit_kernel(const float* __restrict__ as_, const float* __restrict__ ad_,
                                 float* __restrict__ m) {
    int i = blockIdx.x * blockDim.x + threadIdx.x;
    if (i < NN * HEADS) m[i] = lrelu(as_[i] + ad_[i]);
}

__global__ void gat_mmax_kernel(const int* __restrict__ src, const int* __restrict__ dst,
                                const float* __restrict__ as_, const float* __restrict__ ad_,
                                float* __restrict__ m) {
    int i = blockIdx.x * blockDim.x + threadIdx.x;
    if (i >= EDGES * HEADS) return;
    int e = i >> 3, h = i & 7;
    int s = __ldg(&src[e]), d = __ldg(&dst[e]);
    float ev = lrelu(as_[s * HEADS + h] + ad_[d * HEADS + h]);
    atomicMaxFloat(&m[d * HEADS + h], ev);
}

__global__ void gat_ssum_init_kernel(const float* __restrict__ as_, const float* __restrict__ ad_,
                                     const float* __restrict__ m, float* __restrict__ ssum) {
    int i = blockIdx.x * blockDim.x + threadIdx.x;
    if (i < NN * HEADS) ssum[i] = expf(lrelu(as_[i] + ad_[i]) - m[i]);
}

__global__ void gat_ssum_add_kernel(const int* __restrict__ src, const int* __restrict__ dst,
                                    const float* __restrict__ as_, const float* __restrict__ ad_,
                                    const float* __restrict__ m, float* __restrict__ ssum) {
    int i = blockIdx.x * blockDim.x + threadIdx.x;
    if (i >= EDGES * HEADS) return;
    int e = i >> 3, h = i & 7;
    int s = __ldg(&src[e]), d = __ldg(&dst[e]);
    float ev = lrelu(as_[s * HEADS + h] + ad_[d * HEADS + h]);
    atomicAdd(&ssum[d * HEADS + h], expf(ev - m[d * HEADS + h]));
}

__global__ void gat_out_init_kernel(const float* __restrict__ hg, const float* __restrict__ as_,
                                    const float* __restrict__ ad_, const float* __restrict__ m,
                                    const float* __restrict__ ssum, const float* __restrict__ bias,
                                    float* __restrict__ out) {
    int idx = blockIdx.x * 256 + threadIdx.x;  // grid = NN blocks
    int n = idx >> 8, c = idx & 255;
    int h = c >> 5;
    int nh = n * HEADS + h;
    float alpha = expf(lrelu(as_[nh] + ad_[nh]) - m[nh]) / ssum[nh];
    out[idx] = hg[idx] * alpha + bias[c];
}

// 64 threads per edge, float4; head = t>>3
__global__ void gat_scatter_kernel(const float* __restrict__ hg, const int* __restrict__ src,
                                   const int* __restrict__ dst, const float* __restrict__ as_,
                                   const float* __restrict__ ad_, const float* __restrict__ m,
                                   const float* __restrict__ ssum, float* __restrict__ out) {
    unsigned gid = blockIdx.x * 256 + threadIdx.x;
    int e = gid >> 6;
    int t = gid & 63;
    if (e >= EDGES) return;
    int s = __ldg(&src[e]);
    int d = __ldg(&dst[e]);
    int h = t >> 3;
    int snh = s * HEADS + h, dnh = d * HEADS + h;
    float ev = lrelu(__ldg(&as_[snh]) + __ldg(&ad_[dnh]));
    float alpha = expf(ev - __ldg(&m[dnh])) / __ldg(&ssum[dnh]);
    float4 v = *(const float4*)(hg + (size_t)s * HIDD + t * 4);
    float* o = out + (size_t)d * HIDD + t * 4;
    atomicAdd(o + 0, v.x * alpha);
    atomicAdd(o + 1, v.y * alpha);
    atomicAdd(o + 2, v.z * alpha);
    atomicAdd(o + 3, v.w * alpha);
}

// ---------------- LayerNorm (block per node) ----------------
__global__ void ln_kernel(const float* __restrict__ h, const float* __restrict__ g,
                          const float* __restrict__ b, float* __restrict__ out) {
    int n = blockIdx.x, c = threadIdx.x;
    float v = h[(size_t)n * HIDD + c];
    __shared__ float red[8];
    __shared__ float s_mu, s_rstd;

    float s = v;
#pragma unroll
    for (int o = 16; o; o >>= 1) s += __shfl_down_sync(0xffffffffu, s, o);
    if ((c & 31) == 0) red[c >> 5] = s;
    __syncthreads();
    if (c == 0) {
        float t = 0.f;
#pragma unroll
        for (int i = 0; i < 8; i++) t += red[i];
        s_mu = t * (1.0f / HIDD);
    }
    __syncthreads();
    float dv = v - s_mu;
    float q = dv * dv;
#pragma unroll
    for (int o = 16; o; o >>= 1) q += __shfl_down_sync(0xffffffffu, q, o);
    if ((c & 31) == 0) red[c >> 5] = q;
    __syncthreads();
    if (c == 0) {
        float t = 0.f;
#pragma unroll
        for (int i = 0; i < 8; i++) t += red[i];
        s_rstd = rsqrtf(t * (1.0f / HIDD) + LN_EPS);
    }
    __syncthreads();
    out[(size_t)n * HIDD + c] = dv * s_rstd * g[c] + b[c];
}

// ---------------- fusion ----------------
__global__ void fuse_logits_kernel(const float* __restrict__ t, const float* __restrict__ W2,
                                   const float* __restrict__ b2, float* __restrict__ w) {
    int gw = (blockIdx.x * blockDim.x + threadIdx.x) >> 5;
    int lane = threadIdx.x & 31;
    if (gw >= NN) return;
    const float* row = t + (size_t)gw * HIDD;
    float a0 = 0.f, a1 = 0.f, a2 = 0.f, a3 = 0.f;
    for (int c = lane; c < HIDD; c += 32) {
        float tv = row[c];
        a0 += tv * W2[c * 4 + 0];
        a1 += tv * W2[c * 4 + 1];
        a2 += tv * W2[c * 4 + 2];
        a3 += tv * W2[c * 4 + 3];
    }
#pragma unroll
    for (int o = 16; o; o >>= 1) {
        a0 += __shfl_down_sync(0xffffffffu, a0, o);
        a1 += __shfl_down_sync(0xffffffffu, a1, o);
        a2 += __shfl_down_sync(0xffffffffu, a2, o);
        a3 += __shfl_down_sync(0xffffffffu, a3, o);
    }
    if (lane == 0) {
        float l0 = a0 + b2[0], l1 = a1 + b2[1], l2 = a2 + b2[2], l3 = a3 + b2[3];
        float mx = fmaxf(fmaxf(l0, l1), fmaxf(l2, l3));
        float e0 = expf(l0 - mx), e1 = expf(l1 - mx), e2 = expf(l2 - mx), e3 = expf(l3 - mx);
        float inv = 1.0f / (e0 + e1 + e2 + e3);
        w[gw * 4 + 0] = e0 * inv;
        w[gw * 4 + 1] = e1 * inv;
        w[gw * 4 + 2] = e2 * inv;
        w[gw * 4 + 3] = e3 * inv;
    }
}

__global__ void combine_kernel(const float* __restrict__ w, float* __restrict__ out) {
    int idx = blockIdx.x * 256 + threadIdx.x;  // grid = NN blocks
    int n = idx >> 8;
    float acc = 0.f;
#pragma unroll
    for (int k = 0; k < KK; k++) acc += w[n * KK + k] * g_outs[(size_t)k * NN * HIDD + idx];
    out[idx] = acc;
}

// ---------------- host ----------------
extern "C" void kernel_launch(void* const* d_in, const int* in_sizes, int n_in,
                              void* d_out, int out_size) {
    const float *x, *style, *stress;
    const int* ei[KK];
    int base;
    if (in_sizes[1] == 2 * EDGES) {
        x = (const float*)d_in[0];
        for (int k = 0; k < KK; k++) ei[k] = (const int*)d_in[1 + k];
        style = (const float*)d_in[5];
        stress = (const float*)d_in[6];
        base = 7;
    } else {
        x = (const float*)d_in[0];
        style = (const float*)d_in[1];
        stress = (const float*)d_in[2];
        for (int k = 0; k < KK; k++) ei[k] = (const int*)d_in[3 + k];
        base = 7;
    }
    const float* gW0 = (const float*)d_in[base + 0];
    const float* gb0 = (const float*)d_in[base + 1];
    const float* gW1 = (const float*)d_in[base + 2];
    const float* gb1 = (const float*)d_in[base + 3];
    const float* gW2 = (const float*)d_in[base + 4];
    const float* gb2 = (const float*)d_in[base + 5];
    const float* aW  = (const float*)d_in[base + 6];
    const float* aas = (const float*)d_in[base + 7];
    const float* aad = (const float*)d_in[base + 8];
    const float* ab  = (const float*)d_in[base + 9];
    const float* lg  = (const float*)d_in[base + 10];
    const float* lb  = (const float*)d_in[base + 11];
    const float* fW1 = (const float*)d_in[base + 12];
    const float* fb1 = (const float*)d_in[base + 13];
    const float* fW2 = (const float*)d_in[base + 14];
    const float* fb2 = (const float*)d_in[base + 15];

    float *h0, *h1, *h2, *h3, *outs, *dinv, *as_, *ad_, *m_, *ssum_, *wbuf;
    cudaGetSymbolAddress((void**)&h0, g_h0);
    cudaGetSymbolAddress((void**)&h1, g_h1);
    cudaGetSymbolAddress((void**)&h2, g_h2);
    cudaGetSymbolAddress((void**)&h3, g_h3);
    cudaGetSymbolAddress((void**)&outs, g_outs);
    cudaGetSymbolAddress((void**)&dinv, g_dinv);
    cudaGetSymbolAddress((void**)&as_, g_as);
    cudaGetSymbolAddress((void**)&ad_, g_ad);
    cudaGetSymbolAddress((void**)&m_, g_m);
    cudaGetSymbolAddress((void**)&ssum_, g_ssum);
    cudaGetSymbolAddress((void**)&wbuf, g_w);

    dim3 ggrid(HIDD / TN, cdiv(NN, TM));
    const int escatter_blocks = cdiv(EDGES * 64, 256);

    for (int k = 0; k < KK; k++) {
        const int* src = ei[k];
        const int* dst = ei[k] + EDGES;

        fill_kernel<<<cdiv(NN, 256), 256>>>(dinv, 1.0f, NN);
        deg_count_kernel<<<cdiv(EDGES, 256), 256>>>(dst, dinv, EDGES);
        rsqrt_kernel<<<cdiv(NN, 256), 256>>>(dinv, NN);

        // GCN L0: h1 = x@W0 ; h2 = h1*dinv^2 + b (fused) ; scatter h1 -> h2
        gemm128_kernel<<<ggrid, 256>>>(x, gW0 + (size_t)k * IN_DIM * HIDD, h1,
                                       NN, IN_DIM, HIDD, 0, h2, dinv, gb0 + k * HIDD);
        gcn_scatter_kernel<<<escatter_blocks, 256>>>(h1, src, dst, dinv, h2);

        // GCN L1: A = relu(h2) -> h1 ; init h3 ; scatter h1 -> h3   (no aliasing)
        gemm128_kernel<<<ggrid, 256>>>(h2, gW1 + (size_t)k * HIDD * HIDD, h1,
                                       NN, HIDD, HIDD, 2, h3, dinv, gb1 + k * HIDD);
        gcn_scatter_kernel<<<escatter_blocks, 256>>>(h1, src, dst, dinv, h3);

        // GCN L2: A = relu(h3) -> h1 ; init h2 ; scatter h1 -> h2
        gemm128_kernel<<<ggrid, 256>>>(h3, gW2 + (size_t)k * HIDD * HIDD, h1,
                                       NN, HIDD, HIDD, 2, h2, dinv, gb2 + k * HIDD);
        gcn_scatter_kernel<<<escatter_blocks, 256>>>(h1, src, dst, dinv, h2);

        // GAT: A = relu(h2) -> h1
        gemm128_kernel<<<ggrid, 256>>>(h2, aW + (size_t)k * HIDD * HIDD, h1,
                                       NN, HIDD, HIDD, 2, nullptr, nullptr, nullptr);
        gat_asad_kernel<<<NN, 256>>>(h1, aas + k * HEADS * HC, aad + k * HEADS * HC, as_, ad_);
        gat_minit_kernel<<<cdiv(NN * HEADS, 256), 256>>>(as_, ad_, m_);
        gat_mmax_kernel<<<cdiv(EDGES * HEADS, 256), 256>>>(src, dst, as_, ad_, m_);
        gat_ssum_init_kernel<<<cdiv(NN * HEADS, 256), 256>>>(as_, ad_, m_, ssum_);
        gat_ssum_add_kernel<<<cdiv(EDGES * HEADS, 256), 256>>>(src, dst, as_, ad_, m_, ssum_);
        gat_out_init_kernel<<<NN, 256>>>(h1, as_, ad_, m_, ssum_, ab + k * HIDD, h0);
        gat_scatter_kernel<<<escatter_blocks, 256>>>(h1, src, dst, as_, ad_, m_, ssum_, h0);

        ln_kernel<<<NN, 256>>>(h0, lg + k * HIDD, lb + k * HIDD, outs + (size_t)k * NN * HIDD);
    }

    // fusion
    gemm128_kernel<<<ggrid, 256>>>(style, fW1, h1, NN, HIDD, HIDD, 0, nullptr, nullptr, nullptr);
    gemm128_kernel<<<ggrid, 256>>>(stress, fW1 + (size_t)HIDD * HIDD, h1, NN, HIDD, HIDD, 1,
                                   nullptr, nullptr, nullptr);
    tanh_bias_kernel<<<NN, 256>>>(h1, fb1);
    fuse_logits_kernel<<<cdiv(NN * 32, 256), 256>>>(h1, fW2, fb2, wbuf);
    combine_kernel<<<NN, 256>>>(wbuf, (float*)d_out);
}

// round 5
// speedup vs baseline: 2.3777x; 1.1606x over previous
#include <cuda_runtime.h>
#include <cuda_bf16.h>
#include <math.h>
#include <stdint.h>

#define NN 50000
#define IN_DIM 512
#define HIDD 256
#define HEADS 8
#define HC 32
#define EDGES 600000
#define KK 4
#define LN_EPS 1e-5f

// ---------------- scratch (static device globals; no allocation) ----------------
__device__ float g_h0[NN * HIDD];
__device__ float g_h1[NN * HIDD];
__device__ float g_h2[NN * HIDD];
__device__ float g_h3[NN * HIDD];
__device__ float g_outs[KK * NN * HIDD];
__device__ float g_dinv[NN];
__device__ float g_as[NN * HEADS];
__device__ float g_ad[NN * HEADS];
__device__ float g_m[NN * HEADS];
__device__ float g_ssum[NN * HEADS];
__device__ float g_w[NN * KK];
// pre-split weights, bf16 hi/lo, [n][k] layout per 32-k chunk:
// chunk c base = c*16384; hi at [n*32+kin], lo at +8192.  total 88*32768 elems
__device__ __nv_bfloat16 g_bsplit[88 * 32768];

__device__ __forceinline__ float lrelu(float x) { return x > 0.f ? x : 0.2f * x; }

__device__ __forceinline__ void atomicMaxFloat(float* addr, float value) {
    int* ai = (int*)addr;
    int old = *ai;
    while (__int_as_float(old) < value) {
        int assumed = old;
        old = atomicCAS(ai, assumed, __float_as_int(value));
        if (old == assumed) break;
    }
}

static inline int cdiv(int a, int b) { return (a + b - 1) / b; }

__device__ __forceinline__ uint32_t pk_bf16x2(__nv_bfloat16 a, __nv_bfloat16 b) {
    return (uint32_t)__bfloat16_as_ushort(a) | ((uint32_t)__bfloat16_as_ushort(b) << 16);
}

// mma.sync m16n8k16 bf16 (portable HMMA, sm_80+)
__device__ __forceinline__ void mma16816(float* c, const uint32_t* a, const uint32_t* b) {
    asm volatile(
        "mma.sync.aligned.m16n8k16.row.col.f32.bf16.bf16.f32 "
        "{%0,%1,%2,%3}, {%4,%5,%6,%7}, {%8,%9}, {%0,%1,%2,%3};"
        : "+f"(c[0]), "+f"(c[1]), "+f"(c[2]), "+f"(c[3])
        : "r"(a[0]), "r"(a[1]), "r"(a[2]), "r"(a[3]), "r"(b[0]), "r"(b[1]));
}

// ---------------- precompute: W[Kd,256] -> bf16 hi/lo, [n][k] per 32-k chunk ----------------
__global__ void bsplit_kernel(const float* __restrict__ W, __nv_bfloat16* __restrict__ dst,
                              int total) {
    int idx = blockIdx.x * 256 + threadIdx.x;
    if (idx >= total) return;
    int kk = idx >> 8;      // k index
    int n = idx & 255;      // n index
    float w = W[idx];
    __nv_bfloat16 hi = __float2bfloat16_rn(w);
    __nv_bfloat16 lo = __float2bfloat16_rn(w - __bfloat162float(hi));
    int chunk = kk >> 5, kin = kk & 31;
    __nv_bfloat16* base = dst + (size_t)chunk * 16384;
    base[n * 32 + kin] = hi;
    base[n * 32 + kin + 8192] = lo;
}

// ---------------- tensor-core GEMM (mma.sync): C[M,256] = op(A)[M,Kd] @ W[Kd,256] ----------------
// A = A0 for k<256, A1 for k>=256 (row stride lda). relu on A load (flag).
// out2 (optional): out2[r,c] = C[r,c]*dinv[r]^2 + bias[c]
#define SA 40   // smem row stride in bf16 (80B = 20 banks, conflict-free, 16B-aligned)

__global__ void __launch_bounds__(256)
gemm_tc_kernel(const float* __restrict__ A0, const float* __restrict__ A1, int lda,
               const __nv_bfloat16* __restrict__ Bsw,
               float* __restrict__ C, int M, int Kd, int relu,
               float* __restrict__ out2, const float* __restrict__ dinv,
               const float* __restrict__ bias) {
    __shared__ __align__(16) __nv_bfloat16 As_hi[128 * SA];
    __shared__ __align__(16) __nv_bfloat16 As_lo[128 * SA];
    __shared__ __align__(16) __nv_bfloat16 Bs_hi[128 * SA];
    __shared__ __align__(16) __nv_bfloat16 Bs_lo[128 * SA];

    const int tid = threadIdx.x;
    const int wid = tid >> 5;
    const int lane = tid & 31;
    const int g = lane >> 2;       // group id 0..7
    const int tig = lane & 3;      // thread in group

    const int rowBase = blockIdx.y * 128;
    const int colBase = blockIdx.x * 128;
    const int warp_m = (wid >> 2) * 64;
    const int warp_n = (wid & 3) * 32;

    float acc[4][4][4];
#pragma unroll
    for (int i = 0; i < 4; i++)
#pragma unroll
        for (int j = 0; j < 4; j++)
#pragma unroll
            for (int q = 0; q < 4; q++) acc[i][j][q] = 0.f;

    const int srow = tid >> 1;        // staging row 0..127
    const int shalf = tid & 1;        // which 16-k half

    const int nChunks = Kd >> 5;
    for (int c = 0; c < nChunks; c++) {
        int k0 = c << 5;
        const float* Ap;
        int kloc;
        if (k0 < 256) { Ap = A0; kloc = k0; } else { Ap = A1; kloc = k0 - 256; }

        // ---- stage A: 128 rows x 32 k fp32 -> bf16 hi/lo ----
        {
            int rg = rowBase + srow;
            int kb = kloc + shalf * 16;
            uint32_t so = srow * SA + shalf * 16;
#pragma unroll
            for (int j = 0; j < 4; j++) {
                float4 av = make_float4(0.f, 0.f, 0.f, 0.f);
                if (rg < M) av = *(const float4*)(Ap + (size_t)rg * lda + kb + j * 4);
                if (relu) {
                    av.x = fmaxf(av.x, 0.f); av.y = fmaxf(av.y, 0.f);
                    av.z = fmaxf(av.z, 0.f); av.w = fmaxf(av.w, 0.f);
                }
                __nv_bfloat16 h0 = __float2bfloat16_rn(av.x);
                __nv_bfloat16 h1 = __float2bfloat16_rn(av.y);
                __nv_bfloat16 h2 = __float2bfloat16_rn(av.z);
                __nv_bfloat16 h3 = __float2bfloat16_rn(av.w);
                __nv_bfloat16 l0 = __float2bfloat16_rn(av.x - __bfloat162float(h0));
                __nv_bfloat16 l1 = __float2bfloat16_rn(av.y - __bfloat162float(h1));
                __nv_bfloat16 l2 = __float2bfloat16_rn(av.z - __bfloat162float(h2));
                __nv_bfloat16 l3 = __float2bfloat16_rn(av.w - __bfloat162float(h3));
                *(uint2*)&As_hi[so + j * 4] = make_uint2(pk_bf16x2(h0, h1), pk_bf16x2(h2, h3));
                *(uint2*)&As_lo[so + j * 4] = make_uint2(pk_bf16x2(l0, l1), pk_bf16x2(l2, l3));
            }
        }
        // ---- stage B: coalesced copy of pre-split [n][k] ----
        {
            const __nv_bfloat16* Bc = Bsw + (size_t)c * 16384 + (size_t)(colBase + srow) * 32 + shalf * 16;
            uint32_t so = srow * SA + shalf * 16;
            uint4 v0 = *(const uint4*)(Bc);
            uint4 v1 = *(const uint4*)(Bc + 8);
            *(uint4*)&Bs_hi[so] = v0;
            *(uint4*)&Bs_hi[so + 8] = v1;
            uint4 w0 = *(const uint4*)(Bc + 8192);
            uint4 w1 = *(const uint4*)(Bc + 8200);
            *(uint4*)&Bs_lo[so] = w0;
            *(uint4*)&Bs_lo[so + 8] = w1;
        }
        __syncthreads();

        // ---- compute: 2 k-steps of 16 ----
#pragma unroll
        for (int ks = 0; ks < 2; ks++) {
            uint32_t ah[4][4], al[4][4];
#pragma unroll
            for (int mt = 0; mt < 4; mt++) {
                uint32_t b0 = (warp_m + mt * 16 + g) * SA + ks * 16 + tig * 2;
                ah[mt][0] = *(const uint32_t*)&As_hi[b0];
                ah[mt][1] = *(const uint32_t*)&As_hi[b0 + 8 * SA];
                ah[mt][2] = *(const uint32_t*)&As_hi[b0 + 8];
                ah[mt][3] = *(const uint32_t*)&As_hi[b0 + 8 * SA + 8];
                al[mt][0] = *(const uint32_t*)&As_lo[b0];
                al[mt][1] = *(const uint32_t*)&As_lo[b0 + 8 * SA];
                al[mt][2] = *(const uint32_t*)&As_lo[b0 + 8];
                al[mt][3] = *(const uint32_t*)&As_lo[b0 + 8 * SA + 8];
            }
            uint32_t bh[4][2], bl[4][2];
#pragma unroll
            for (int nt = 0; nt < 4; nt++) {
                uint32_t b0 = (warp_n + nt * 8 + g) * SA + ks * 16 + tig * 2;
                bh[nt][0] = *(const uint32_t*)&Bs_hi[b0];
                bh[nt][1] = *(const uint32_t*)&Bs_hi[b0 + 8];
                bl[nt][0] = *(const uint32_t*)&Bs_lo[b0];
                bl[nt][1] = *(const uint32_t*)&Bs_lo[b0 + 8];
            }
#pragma unroll
            for (int mt = 0; mt < 4; mt++)
#pragma unroll
                for (int nt = 0; nt < 4; nt++) {
                    mma16816(acc[mt][nt], ah[mt], bh[nt]);
                    mma16816(acc[mt][nt], ah[mt], bl[nt]);
                    mma16816(acc[mt][nt], al[mt], bh[nt]);
                }
        }
        __syncthreads();
    }

    // ---- epilogue ----
    const bool has2 = (out2 != nullptr);
#pragma unroll
    for (int mt = 0; mt < 4; mt++) {
        int row0 = rowBase + warp_m + mt * 16 + g;
        int row1 = row0 + 8;
        float d0 = 0.f, d1 = 0.f;
        if (has2) {
            if (row0 < M) { float di = dinv[row0]; d0 = di * di; }
            if (row1 < M) { float di = dinv[row1]; d1 = di * di; }
        }
#pragma unroll
        for (int nt = 0; nt < 4; nt++) {
            int col = colBase + warp_n + nt * 8 + tig * 2;
            float* cr;
            if (row0 < M) {
                cr = C + (size_t)row0 * 256 + col;
                *(float2*)cr = make_float2(acc[mt][nt][0], acc[mt][nt][1]);
                if (has2) {
                    *(float2*)(out2 + (size_t)row0 * 256 + col) =
                        make_float2(acc[mt][nt][0] * d0 + bias[col],
                                    acc[mt][nt][1] * d0 + bias[col + 1]);
                }
            }
            if (row1 < M) {
                cr = C + (size_t)row1 * 256 + col;
                *(float2*)cr = make_float2(acc[mt][nt][2], acc[mt][nt][3]);
                if (has2) {
                    *(float2*)(out2 + (size_t)row1 * 256 + col) =
                        make_float2(acc[mt][nt][2] * d1 + bias[col],
                                    acc[mt][nt][3] * d1 + bias[col + 1]);
                }
            }
        }
    }
}

// ---------------- elementwise / graph kernels (unchanged from passing round) ----------------
__global__ void fill_kernel(float* p, float v, int n) {
    int i = blockIdx.x * blockDim.x + threadIdx.x;
    if (i < n) p[i] = v;
}

__global__ void deg_count_kernel(const int* __restrict__ dst, float* __restrict__ deg, int e) {
    int i = blockIdx.x * blockDim.x + threadIdx.x;
    if (i < e) atomicAdd(&deg[dst[i]], 1.0f);
}

__global__ void rsqrt_kernel(float* p, int n) {
    int i = blockIdx.x * blockDim.x + threadIdx.x;
    if (i < n) p[i] = rsqrtf(p[i]);
}

__global__ void tanh_bias_kernel(float* __restrict__ t, const float* __restrict__ b) {
    int idx = blockIdx.x * 256 + threadIdx.x;
    int c = idx & (HIDD - 1);
    t[idx] = tanhf(t[idx] + b[c]);
}

__global__ void gcn_scatter_kernel(const float* __restrict__ h, const int* __restrict__ src,
                                   const int* __restrict__ dst, const float* __restrict__ dinv,
                                   float* __restrict__ out) {
    unsigned gid = blockIdx.x * 256 + threadIdx.x;
    int e = gid >> 6;
    int t = gid & 63;
    if (e >= EDGES) return;
    int s = __ldg(&src[e]);
    int d = __ldg(&dst[e]);
    float coef = __ldg(&dinv[s]) * __ldg(&dinv[d]);
    float4 v = *(const float4*)(h + (size_t)s * HIDD + t * 4);
    float* o = out + (size_t)d * HIDD + t * 4;
    atomicAdd(o + 0, v.x * coef);
    atomicAdd(o + 1, v.y * coef);
    atomicAdd(o + 2, v.z * coef);
    atomicAdd(o + 3, v.w * coef);
}

__global__ void gat_asad_kernel(const float* __restrict__ hg, const float* __restrict__ asrc,
                                const float* __restrict__ adst, float* __restrict__ as_,
                                float* __restrict__ ad_) {
    int n = blockIdx.x;
    int h = threadIdx.x >> 5, c = threadIdx.x & 31;
    float v = hg[(size_t)n * HIDD + h * HC + c];
    float s = v * asrc[h * HC + c];
    float d = v * adst[h * HC + c];
#pragma unroll
    for (int o = 16; o; o >>= 1) {
        s += __shfl_down_sync(0xffffffffu, s, o);
        d += __shfl_down_sync(0xffffffffu, d, o);
    }
    if (c == 0) {
        as_[n * HEADS + h] = s;
        ad_[n * HEADS + h] = d;
    }
}

__global__ void gat_minit_kernel(const float* __restrict__ as_, const float* __restrict__ ad_,
                                 float* __restrict__ m) {
    int i = blockIdx.x * blockDim.x + threadIdx.x;
    if (i < NN * HEADS) m[i] = lrelu(as_[i] + ad_[i]);
}

__global__ void gat_mmax_kernel(const int* __restrict__ src, const int* __restrict__ dst,
                                const float* __restrict__ as_, const float* __restrict__ ad_,
                                float* __restrict__ m) {
    int i = blockIdx.x * blockDim.x + threadIdx.x;
    if (i >= EDGES * HEADS) return;
    int e = i >> 3, h = i & 7;
    int s = __ldg(&src[e]), d = __ldg(&dst[e]);
    float ev = lrelu(as_[s * HEADS + h] + ad_[d * HEADS + h]);
    atomicMaxFloat(&m[d * HEADS + h], ev);
}

__global__ void gat_ssum_init_kernel(const float* __restrict__ as_, const float* __restrict__ ad_,
                                     const float* __restrict__ m, float* __restrict__ ssum) {
    int i = blockIdx.x * blockDim.x + threadIdx.x;
    if (i < NN * HEADS) ssum[i] = expf(lrelu(as_[i] + ad_[i]) - m[i]);
}

__global__ void gat_ssum_add_kernel(const int* __restrict__ src, const int* __restrict__ dst,
                                    const float* __restrict__ as_, const float* __restrict__ ad_,
                                    const float* __restrict__ m, float* __restrict__ ssum) {
    int i = blockIdx.x * blockDim.x + threadIdx.x;
    if (i >= EDGES * HEADS) return;
    int e = i >> 3, h = i & 7;
    int s = __ldg(&src[e]), d = __ldg(&dst[e]);
    float ev = lrelu(as_[s * HEADS + h] + ad_[d * HEADS + h]);
    atomicAdd(&ssum[d * HEADS + h], expf(ev - m[d * HEADS + h]));
}

__global__ void gat_out_init_kernel(const float* __restrict__ hg, const float* __restrict__ as_,
                                    const float* __restrict__ ad_, const float* __restrict__ m,
                                    const float* __restrict__ ssum, const float* __restrict__ bias,
                                    float* __restrict__ out) {
    int idx = blockIdx.x * 256 + threadIdx.x;
    int n = idx >> 8, c = idx & 255;
    int h = c >> 5;
    int nh = n * HEADS + h;
    float alpha = expf(lrelu(as_[nh] + ad_[nh]) - m[nh]) / ssum[nh];
    out[idx] = hg[idx] * alpha + bias[c];
}

__global__ void gat_scatter_kernel(const float* __restrict__ hg, const int* __restrict__ src,
                                   const int* __restrict__ dst, const float* __restrict__ as_,
                                   const float* __restrict__ ad_, const float* __restrict__ m,
                                   const float* __restrict__ ssum, float* __restrict__ out) {
    unsigned gid = blockIdx.x * 256 + threadIdx.x;
    int e = gid >> 6;
    int t = gid & 63;
    if (e >= EDGES) return;
    int s = __ldg(&src[e]);
    int d = __ldg(&dst[e]);
    int h = t >> 3;
    int snh = s * HEADS + h, dnh = d * HEADS + h;
    float ev = lrelu(__ldg(&as_[snh]) + __ldg(&ad_[dnh]));
    float alpha = expf(ev - __ldg(&m[dnh])) / __ldg(&ssum[dnh]);
    float4 v = *(const float4*)(hg + (size_t)s * HIDD + t * 4);
    float* o = out + (size_t)d * HIDD + t * 4;
    atomicAdd(o + 0, v.x * alpha);
    atomicAdd(o + 1, v.y * alpha);
    atomicAdd(o + 2, v.z * alpha);
    atomicAdd(o + 3, v.w * alpha);
}

__global__ void ln_kernel(const float* __restrict__ h, const float* __restrict__ g,
                          const float* __restrict__ b, float* __restrict__ out) {
    int n = blockIdx.x, c = threadIdx.x;
    float v = h[(size_t)n * HIDD + c];
    __shared__ float red[8];
    __shared__ float s_mu, s_rstd;

    float s = v;
#pragma unroll
    for (int o = 16; o; o >>= 1) s += __shfl_down_sync(0xffffffffu, s, o);
    if ((c & 31) == 0) red[c >> 5] = s;
    __syncthreads();
    if (c == 0) {
        float t = 0.f;
#pragma unroll
        for (int i = 0; i < 8; i++) t += red[i];
        s_mu = t * (1.0f / HIDD);
    }
    __syncthreads();
    float dv = v - s_mu;
    float q = dv * dv;
#pragma unroll
    for (int o = 16; o; o >>= 1) q += __shfl_down_sync(0xffffffffu, q, o);
    if ((c & 31) == 0) red[c >> 5] = q;
    __syncthreads();
    if (c == 0) {
        float t = 0.f;
#pragma unroll
        for (int i = 0; i < 8; i++) t += red[i];
        s_rstd = rsqrtf(t * (1.0f / HIDD) + LN_EPS);
    }
    __syncthreads();
    out[(size_t)n * HIDD + c] = dv * s_rstd * g[c] + b[c];
}

__global__ void fuse_logits_kernel(const float* __restrict__ t, const float* __restrict__ W2,
                                   const float* __restrict__ b2, float* __restrict__ w) {
    int gw = (blockIdx.x * blockDim.x + threadIdx.x) >> 5;
    int lane = threadIdx.x & 31;
    if (gw >= NN) return;
    const float* row = t + (size_t)gw * HIDD;
    float a0 = 0.f, a1 = 0.f, a2 = 0.f, a3 = 0.f;
    for (int c = lane; c < HIDD; c += 32) {
        float tv = row[c];
        a0 += tv * W2[c * 4 + 0];
        a1 += tv * W2[c * 4 + 1];
        a2 += tv * W2[c * 4 + 2];
        a3 += tv * W2[c * 4 + 3];
    }
#pragma unroll
    for (int o = 16; o; o >>= 1) {
        a0 += __shfl_down_sync(0xffffffffu, a0, o);
        a1 += __shfl_down_sync(0xffffffffu, a1, o);
        a2 += __shfl_down_sync(0xffffffffu, a2, o);
        a3 += __shfl_down_sync(0xffffffffu, a3, o);
    }
    if (lane == 0) {
        float l0 = a0 + b2[0], l1 = a1 + b2[1], l2 = a2 + b2[2], l3 = a3 + b2[3];
        float mx = fmaxf(fmaxf(l0, l1), fmaxf(l2, l3));
        float e0 = expf(l0 - mx), e1 = expf(l1 - mx), e2 = expf(l2 - mx), e3 = expf(l3 - mx);
        float inv = 1.0f / (e0 + e1 + e2 + e3);
        w[gw * 4 + 0] = e0 * inv;
        w[gw * 4 + 1] = e1 * inv;
        w[gw * 4 + 2] = e2 * inv;
        w[gw * 4 + 3] = e3 * inv;
    }
}

__global__ void combine_kernel(const float* __restrict__ w, float* __restrict__ out) {
    int idx = blockIdx.x * 256 + threadIdx.x;
    int n = idx >> 8;
    float acc = 0.f;
#pragma unroll
    for (int k = 0; k < KK; k++) acc += w[n * KK + k] * g_outs[(size_t)k * NN * HIDD + idx];
    out[idx] = acc;
}

// ---------------- host ----------------
extern "C" void kernel_launch(void* const* d_in, const int* in_sizes, int n_in,
                              void* d_out, int out_size) {
    const float *x, *style, *stress;
    const int* ei[KK];
    int base;
    if (in_sizes[1] == 2 * EDGES) {
        x = (const float*)d_in[0];
        for (int k = 0; k < KK; k++) ei[k] = (const int*)d_in[1 + k];
        style = (const float*)d_in[5];
        stress = (const float*)d_in[6];
        base = 7;
    } else {
        x = (const float*)d_in[0];
        style = (const float*)d_in[1];
        stress = (const float*)d_in[2];
        for (int k = 0; k < KK; k++) ei[k] = (const int*)d_in[3 + k];
        base = 7;
    }
    const float* gW0 = (const float*)d_in[base + 0];
    const float* gb0 = (const float*)d_in[base + 1];
    const float* gW1 = (const float*)d_in[base + 2];
    const float* gb1 = (const float*)d_in[base + 3];
    const float* gW2 = (const float*)d_in[base + 4];
    const float* gb2 = (const float*)d_in[base + 5];
    const float* aW  = (const float*)d_in[base + 6];
    const float* aas = (const float*)d_in[base + 7];
    const float* aad = (const float*)d_in[base + 8];
    const float* ab  = (const float*)d_in[base + 9];
    const float* lg  = (const float*)d_in[base + 10];
    const float* lb  = (const float*)d_in[base + 11];
    const float* fW1 = (const float*)d_in[base + 12];
    const float* fb1 = (const float*)d_in[base + 13];
    const float* fW2 = (const float*)d_in[base + 14];
    const float* fb2 = (const float*)d_in[base + 15];

    float *h0, *h1, *h2, *h3, *outs, *dinv, *as_, *ad_, *m_, *ssum_, *wbuf;
    __nv_bfloat16* bsw;
    cudaGetSymbolAddress((void**)&h0, g_h0);
    cudaGetSymbolAddress((void**)&h1, g_h1);
    cudaGetSymbolAddress((void**)&h2, g_h2);
    cudaGetSymbolAddress((void**)&h3, g_h3);
    cudaGetSymbolAddress((void**)&outs, g_outs);
    cudaGetSymbolAddress((void**)&dinv, g_dinv);
    cudaGetSymbolAddress((void**)&as_, g_as);
    cudaGetSymbolAddress((void**)&ad_, g_ad);
    cudaGetSymbolAddress((void**)&m_, g_m);
    cudaGetSymbolAddress((void**)&ssum_, g_ssum);
    cudaGetSymbolAddress((void**)&wbuf, g_w);
    cudaGetSymbolAddress((void**)&bsw, g_bsplit);

    // element offsets into g_bsplit (bf16 units): per topo 655360 (W0:512k=262144, others 131072)
    const size_t TOPO = 655360, OW1 = 262144, OW2 = 393216, OAW = 524288, OFUS = 2621440;

    dim3 ggrid(2, cdiv(NN, 128));
    const int escatter_blocks = cdiv(EDGES * 64, 256);

    // precompute split weights
    for (int k = 0; k < KK; k++) {
        __nv_bfloat16* tb = bsw + (size_t)k * TOPO;
        bsplit_kernel<<<cdiv(IN_DIM * HIDD, 256), 256>>>(gW0 + (size_t)k * IN_DIM * HIDD, tb, IN_DIM * HIDD);
        bsplit_kernel<<<cdiv(HIDD * HIDD, 256), 256>>>(gW1 + (size_t)k * HIDD * HIDD, tb + OW1, HIDD * HIDD);
        bsplit_kernel<<<cdiv(HIDD * HIDD, 256), 256>>>(gW2 + (size_t)k * HIDD * HIDD, tb + OW2, HIDD * HIDD);
        bsplit_kernel<<<cdiv(HIDD * HIDD, 256), 256>>>(aW + (size_t)k * HIDD * HIDD, tb + OAW, HIDD * HIDD);
    }
    bsplit_kernel<<<cdiv(2 * HIDD * HIDD, 256), 256>>>(fW1, bsw + OFUS, 2 * HIDD * HIDD);

    for (int k = 0; k < KK; k++) {
        const int* src = ei[k];
        const int* dst = ei[k] + EDGES;
        const __nv_bfloat16* tb = bsw + (size_t)k * TOPO;

        fill_kernel<<<cdiv(NN, 256), 256>>>(dinv, 1.0f, NN);
        deg_count_kernel<<<cdiv(EDGES, 256), 256>>>(dst, dinv, EDGES);
        rsqrt_kernel<<<cdiv(NN, 256), 256>>>(dinv, NN);

        // GCN L0: h1 = x@W0; h2 = h1*dinv^2 + b; scatter h1 -> h2
        gemm_tc_kernel<<<ggrid, 256>>>(x, x + 256, IN_DIM, tb,
                                       h1, NN, IN_DIM, 0, h2, dinv, gb0 + k * HIDD);
        gcn_scatter_kernel<<<escatter_blocks, 256>>>(h1, src, dst, dinv, h2);

        // GCN L1: relu(h2)@W1 -> h1 ; init h3 ; scatter h1 -> h3
        gemm_tc_kernel<<<ggrid, 256>>>(h2, h2, HIDD, tb + OW1,
                                       h1, NN, HIDD, 1, h3, dinv, gb1 + k * HIDD);
        gcn_scatter_kernel<<<escatter_blocks, 256>>>(h1, src, dst, dinv, h3);

        // GCN L2: relu(h3)@W2 -> h1 ; init h2 ; scatter h1 -> h2
        gemm_tc_kernel<<<ggrid, 256>>>(h3, h3, HIDD, tb + OW2,
                                       h1, NN, HIDD, 1, h2, dinv, gb2 + k * HIDD);
        gcn_scatter_kernel<<<escatter_blocks, 256>>>(h1, src, dst, dinv, h2);

        // GAT: relu(h2)@aW -> h1
        gemm_tc_kernel<<<ggrid, 256>>>(h2, h2, HIDD, tb + OAW,
                                       h1, NN, HIDD, 1, nullptr, nullptr, nullptr);
        gat_asad_kernel<<<NN, 256>>>(h1, aas + k * HEADS * HC, aad + k * HEADS * HC, as_, ad_);
        gat_minit_kernel<<<cdiv(NN * HEADS, 256), 256>>>(as_, ad_, m_);
        gat_mmax_kernel<<<cdiv(EDGES * HEADS, 256), 256>>>(src, dst, as_, ad_, m_);
        gat_ssum_init_kernel<<<cdiv(NN * HEADS, 256), 256>>>(as_, ad_, m_, ssum_);
        gat_ssum_add_kernel<<<cdiv(EDGES * HEADS, 256), 256>>>(src, dst, as_, ad_, m_, ssum_);
        gat_out_init_kernel<<<NN, 256>>>(h1, as_, ad_, m_, ssum_, ab + k * HIDD, h0);
        gat_scatter_kernel<<<escatter_blocks, 256>>>(h1, src, dst, as_, ad_, m_, ssum_, h0);

        ln_kernel<<<NN, 256>>>(h0, lg + k * HIDD, lb + k * HIDD, outs + (size_t)k * NN * HIDD);
    }

    // fusion: h1 = [style, stress] @ fW1 (K=512 via two A pointers)
    gemm_tc_kernel<<<ggrid, 256>>>(style, stress, HIDD, bsw + OFUS,
                                   h1, NN, 2 * HIDD, 0, nullptr, nullptr, nullptr);
    tanh_bias_kernel<<<NN, 256>>>(h1, fb1);
    fuse_logits_kernel<<<cdiv(NN * 32, 256), 256>>>(h1, fW2, fb2, wbuf);
    combine_kernel<<<NN, 256>>>(wbuf, (float*)d_out);
}

// round 6
// speedup vs baseline: 5.1298x; 2.1574x over previous
#include <cuda_runtime.h>
#include <cuda_bf16.h>
#include <math.h>
#include <stdint.h>

#define NN 50000
#define IN_DIM 512
#define HIDD 256
#define HEADS 8
#define HC 32
#define EDGES 600000
#define KK 4
#define LN_EPS 1e-5f
#define SCAN_BLOCKS 49   // ceil(50000/1024)

// ---------------- scratch (static device globals; no allocation) ----------------
__device__ float g_h1[NN * HIDD];
__device__ float g_h2[NN * HIDD];
__device__ float g_h3[NN * HIDD];
__device__ float g_outs[KK * NN * HIDD];
__device__ float g_dinv[NN];
__device__ float g_as[NN * HEADS];
__device__ float g_ad[NN * HEADS];
__device__ float g_w[NN * KK];
__device__ int g_counts[KK * NN];
__device__ int g_off[NN + 1];
__device__ int g_cursor[NN];
__device__ int g_bsum[SCAN_BLOCKS];
__device__ int g_csr[EDGES];
// pre-split weights, bf16 hi/lo, [n][k] layout per 32-k chunk
__device__ __nv_bfloat16 g_bsplit[88 * 32768];

__device__ __forceinline__ float lrelu(float x) { return x > 0.f ? x : 0.2f * x; }
static inline int cdiv(int a, int b) { return (a + b - 1) / b; }

__device__ __forceinline__ uint32_t pk_bf16x2(__nv_bfloat16 a, __nv_bfloat16 b) {
    return (uint32_t)__bfloat16_as_ushort(a) | ((uint32_t)__bfloat16_as_ushort(b) << 16);
}

// mma.sync m16n8k16 bf16 (portable HMMA)
__device__ __forceinline__ void mma16816(float* c, const uint32_t* a, const uint32_t* b) {
    asm volatile(
        "mma.sync.aligned.m16n8k16.row.col.f32.bf16.bf16.f32 "
        "{%0,%1,%2,%3}, {%4,%5,%6,%7}, {%8,%9}, {%0,%1,%2,%3};"
        : "+f"(c[0]), "+f"(c[1]), "+f"(c[2]), "+f"(c[3])
        : "r"(a[0]), "r"(a[1]), "r"(a[2]), "r"(a[3]), "r"(b[0]), "r"(b[1]));
}

// ---------------- weight split: ALL matrices in ONE launch ----------------
// grid.y = 17 segments; y<16: topo=y>>2, which=y&3; y==16: fusion W1
// bf16-elem offsets: TOPO=655360, OW1=262144, OW2=393216, OAW=524288, OFUS=2621440
__global__ void bsplit_all_kernel(const float* __restrict__ gW0, const float* __restrict__ gW1,
                                  const float* __restrict__ gW2, const float* __restrict__ aW,
                                  const float* __restrict__ fW1, __nv_bfloat16* __restrict__ bsw) {
    int seg = blockIdx.y;
    const float* src;
    __nv_bfloat16* dst;
    int total;
    if (seg == 16) {
        src = fW1; dst = bsw + 2621440; total = 512 * 256;
    } else {
        int topo = seg >> 2, which = seg & 3;
        __nv_bfloat16* tb = bsw + (size_t)topo * 655360;
        if (which == 0)      { src = gW0 + (size_t)topo * 512 * 256; dst = tb;          total = 512 * 256; }
        else if (which == 1) { src = gW1 + (size_t)topo * 256 * 256; dst = tb + 262144; total = 256 * 256; }
        else if (which == 2) { src = gW2 + (size_t)topo * 256 * 256; dst = tb + 393216; total = 256 * 256; }
        else                 { src = aW  + (size_t)topo * 256 * 256; dst = tb + 524288; total = 256 * 256; }
    }
    int idx = blockIdx.x * 256 + threadIdx.x;
    if (idx >= total) return;
    int kk = idx >> 8;
    int n = idx & 255;
    float w = src[idx];
    __nv_bfloat16 hi = __float2bfloat16_rn(w);
    __nv_bfloat16 lo = __float2bfloat16_rn(w - __bfloat162float(hi));
    int chunk = kk >> 5, kin = kk & 31;
    __nv_bfloat16* base = dst + (size_t)chunk * 16384;
    base[n * 32 + kin] = hi;
    base[n * 32 + kin + 8192] = lo;
}

// ---------------- CSR build ----------------
__global__ void zero_int_kernel(int* p, int n) {
    int i = blockIdx.x * 256 + threadIdx.x;
    if (i < n) p[i] = 0;
}

__global__ void hist_kernel(const int* __restrict__ dst, int* __restrict__ counts) {
    int i = blockIdx.x * 256 + threadIdx.x;
    if (i < EDGES) atomicAdd(&counts[dst[i]], 1);
}

// per-block inclusive scan (1024) -> scanbuf (g_off), block sums -> g_bsum
__global__ void scanA_kernel(const int* __restrict__ counts, int* __restrict__ scanbuf,
                             int* __restrict__ bsum) {
    __shared__ int sh[1024];
    int b = blockIdx.x, t = threadIdx.x;
    int i = b * 1024 + t;
    int v = (i < NN) ? counts[i] : 0;
    sh[t] = v;
    __syncthreads();
#pragma unroll
    for (int o = 1; o < 1024; o <<= 1) {
        int x = (t >= o) ? sh[t - o] : 0;
        __syncthreads();
        sh[t] += x;
        __syncthreads();
    }
    if (i < NN) scanbuf[i] = sh[t];
    if (t == 1023) bsum[b] = sh[t];
}

// exclusive offsets + cursor init + dinv; off[NN]=EDGES
__global__ void scanC_kernel(const int* __restrict__ counts, int* __restrict__ off,
                             int* __restrict__ cursor, const int* __restrict__ bsum,
                             float* __restrict__ dinv) {
    int b = blockIdx.x, t = threadIdx.x;
    int i = b * 1024 + t;
    if (i >= NN) return;
    int prefix = 0;
    for (int j = 0; j < b; j++) prefix += bsum[j];
    int cnt = counts[i];
    int excl = off[i] - cnt + prefix;   // off currently holds block-inclusive scan
    off[i] = excl;
    cursor[i] = excl;
    dinv[i] = rsqrtf((float)cnt + 1.0f);
    if (i == NN - 1) off[NN] = excl + cnt;
}

__global__ void fillcsr_kernel(const int* __restrict__ src, const int* __restrict__ dst,
                               int* __restrict__ cursor, int* __restrict__ csr) {
    int i = blockIdx.x * 256 + threadIdx.x;
    if (i >= EDGES) return;
    int pos = atomicAdd(&cursor[dst[i]], 1);
    csr[pos] = src[i];
}

// ---------------- tensor-core GEMM (identical to passing round 5) ----------------
#define SA 40

__global__ void __launch_bounds__(256)
gemm_tc_kernel(const float* __restrict__ A0, const float* __restrict__ A1, int lda,
               const __nv_bfloat16* __restrict__ Bsw,
               float* __restrict__ C, int M, int Kd, int relu,
               float* __restrict__ out2, const float* __restrict__ dinv,
               const float* __restrict__ bias) {
    __shared__ __align__(16) __nv_bfloat16 As_hi[128 * SA];
    __shared__ __align__(16) __nv_bfloat16 As_lo[128 * SA];
    __shared__ __align__(16) __nv_bfloat16 Bs_hi[128 * SA];
    __shared__ __align__(16) __nv_bfloat16 Bs_lo[128 * SA];

    const int tid = threadIdx.x;
    const int wid = tid >> 5;
    const int lane = tid & 31;
    const int g = lane >> 2;
    const int tig = lane & 3;

    const int rowBase = blockIdx.y * 128;
    const int colBase = blockIdx.x * 128;
    const int warp_m = (wid >> 2) * 64;
    const int warp_n = (wid & 3) * 32;

    float acc[4][4][4];
#pragma unroll
    for (int i = 0; i < 4; i++)
#pragma unroll
        for (int j = 0; j < 4; j++)
#pragma unroll
            for (int q = 0; q < 4; q++) acc[i][j][q] = 0.f;

    const int srow = tid >> 1;
    const int shalf = tid & 1;

    const int nChunks = Kd >> 5;
    for (int c = 0; c < nChunks; c++) {
        int k0 = c << 5;
        const float* Ap;
        int kloc;
        if (k0 < 256) { Ap = A0; kloc = k0; } else { Ap = A1; kloc = k0 - 256; }

        {
            int rg = rowBase + srow;
            int kb = kloc + shalf * 16;
            uint32_t so = srow * SA + shalf * 16;
#pragma unroll
            for (int j = 0; j < 4; j++) {
                float4 av = make_float4(0.f, 0.f, 0.f, 0.f);
                if (rg < M) av = *(const float4*)(Ap + (size_t)rg * lda + kb + j * 4);
                if (relu) {
                    av.x = fmaxf(av.x, 0.f); av.y = fmaxf(av.y, 0.f);
                    av.z = fmaxf(av.z, 0.f); av.w = fmaxf(av.w, 0.f);
                }
                __nv_bfloat16 h0 = __float2bfloat16_rn(av.x);
                __nv_bfloat16 h1 = __float2bfloat16_rn(av.y);
                __nv_bfloat16 h2 = __float2bfloat16_rn(av.z);
                __nv_bfloat16 h3 = __float2bfloat16_rn(av.w);
                __nv_bfloat16 l0 = __float2bfloat16_rn(av.x - __bfloat162float(h0));
                __nv_bfloat16 l1 = __float2bfloat16_rn(av.y - __bfloat162float(h1));
                __nv_bfloat16 l2 = __float2bfloat16_rn(av.z - __bfloat162float(h2));
                __nv_bfloat16 l3 = __float2bfloat16_rn(av.w - __bfloat162float(h3));
                *(uint2*)&As_hi[so + j * 4] = make_uint2(pk_bf16x2(h0, h1), pk_bf16x2(h2, h3));
                *(uint2*)&As_lo[so + j * 4] = make_uint2(pk_bf16x2(l0, l1), pk_bf16x2(l2, l3));
            }
        }
        {
            const __nv_bfloat16* Bc = Bsw + (size_t)c * 16384 + (size_t)(colBase + srow) * 32 + shalf * 16;
            uint32_t so = srow * SA + shalf * 16;
            uint4 v0 = *(const uint4*)(Bc);
            uint4 v1 = *(const uint4*)(Bc + 8);
            *(uint4*)&Bs_hi[so] = v0;
            *(uint4*)&Bs_hi[so + 8] = v1;
            uint4 w0 = *(const uint4*)(Bc + 8192);
            uint4 w1 = *(const uint4*)(Bc + 8200);
            *(uint4*)&Bs_lo[so] = w0;
            *(uint4*)&Bs_lo[so + 8] = w1;
        }
        __syncthreads();

#pragma unroll
        for (int ks = 0; ks < 2; ks++) {
            uint32_t ah[4][4], al[4][4];
#pragma unroll
            for (int mt = 0; mt < 4; mt++) {
                uint32_t b0 = (warp_m + mt * 16 + g) * SA + ks * 16 + tig * 2;
                ah[mt][0] = *(const uint32_t*)&As_hi[b0];
                ah[mt][1] = *(const uint32_t*)&As_hi[b0 + 8 * SA];
                ah[mt][2] = *(const uint32_t*)&As_hi[b0 + 8];
                ah[mt][3] = *(const uint32_t*)&As_hi[b0 + 8 * SA + 8];
                al[mt][0] = *(const uint32_t*)&As_lo[b0];
                al[mt][1] = *(const uint32_t*)&As_lo[b0 + 8 * SA];
                al[mt][2] = *(const uint32_t*)&As_lo[b0 + 8];
                al[mt][3] = *(const uint32_t*)&As_lo[b0 + 8 * SA + 8];
            }
            uint32_t bh[4][2], bl[4][2];
#pragma unroll
            for (int nt = 0; nt < 4; nt++) {
                uint32_t b0 = (warp_n + nt * 8 + g) * SA + ks * 16 + tig * 2;
                bh[nt][0] = *(const uint32_t*)&Bs_hi[b0];
                bh[nt][1] = *(const uint32_t*)&Bs_hi[b0 + 8];
                bl[nt][0] = *(const uint32_t*)&Bs_lo[b0];
                bl[nt][1] = *(const uint32_t*)&Bs_lo[b0 + 8];
            }
#pragma unroll
            for (int mt = 0; mt < 4; mt++)
#pragma unroll
                for (int nt = 0; nt < 4; nt++) {
                    mma16816(acc[mt][nt], ah[mt], bh[nt]);
                    mma16816(acc[mt][nt], ah[mt], bl[nt]);
                    mma16816(acc[mt][nt], al[mt], bh[nt]);
                }
        }
        __syncthreads();
    }

    const bool has2 = (out2 != nullptr);
#pragma unroll
    for (int mt = 0; mt < 4; mt++) {
        int row0 = rowBase + warp_m + mt * 16 + g;
        int row1 = row0 + 8;
        float d0 = 0.f, d1 = 0.f;
        if (has2) {
            if (row0 < M) { float di = dinv[row0]; d0 = di * di; }
            if (row1 < M) { float di = dinv[row1]; d1 = di * di; }
        }
#pragma unroll
        for (int nt = 0; nt < 4; nt++) {
            int col = colBase + warp_n + nt * 8 + tig * 2;
            if (row0 < M) {
                *(float2*)(C + (size_t)row0 * 256 + col) = make_float2(acc[mt][nt][0], acc[mt][nt][1]);
                if (has2) {
                    *(float2*)(out2 + (size_t)row0 * 256 + col) =
                        make_float2(acc[mt][nt][0] * d0 + bias[col],
                                    acc[mt][nt][1] * d0 + bias[col + 1]);
                }
            }
            if (row1 < M) {
                *(float2*)(C + (size_t)row1 * 256 + col) = make_float2(acc[mt][nt][2], acc[mt][nt][3]);
                if (has2) {
                    *(float2*)(out2 + (size_t)row1 * 256 + col) =
                        make_float2(acc[mt][nt][2] * d1 + bias[col],
                                    acc[mt][nt][3] * d1 + bias[col + 1]);
                }
            }
        }
    }
}

// ---------------- GCN gather (CSR, no atomics): io += sum_in h[s]*dinv[s]*dinv[n] ----------------
__global__ void gcn_gather_kernel(const float* __restrict__ h, const int* __restrict__ csr,
                                  const int* __restrict__ off, const float* __restrict__ dinv,
                                  float* __restrict__ io) {
    int tid = threadIdx.x;
    int n = blockIdx.x * 4 + (tid >> 6);
    int t = tid & 63;
    float4 acc = *(const float4*)(io + (size_t)n * HIDD + t * 4);
    float dn = dinv[n];
    int beg = __ldg(&off[n]), end = __ldg(&off[n + 1]);
    for (int j = beg; j < end; j++) {
        int s = __ldg(&csr[j]);
        float cf = __ldg(&dinv[s]) * dn;
        float4 v = *(const float4*)(h + (size_t)s * HIDD + t * 4);
        acc.x += v.x * cf; acc.y += v.y * cf; acc.z += v.z * cf; acc.w += v.w * cf;
    }
    *(float4*)(io + (size_t)n * HIDD + t * 4) = acc;
}

// ---------------- GAT: per-node scores ----------------
__global__ void gat_asad_kernel(const float* __restrict__ hg, const float* __restrict__ asrc,
                                const float* __restrict__ adst, float* __restrict__ as_,
                                float* __restrict__ ad_) {
    int n = blockIdx.x;
    int h = threadIdx.x >> 5, c = threadIdx.x & 31;
    float v = hg[(size_t)n * HIDD + h * HC + c];
    float s = v * asrc[h * HC + c];
    float d = v * adst[h * HC + c];
#pragma unroll
    for (int o = 16; o; o >>= 1) {
        s += __shfl_down_sync(0xffffffffu, s, o);
        d += __shfl_down_sync(0xffffffffu, d, o);
    }
    if (c == 0) {
        as_[n * HEADS + h] = s;
        ad_[n * HEADS + h] = d;
    }
}

// ---------------- GAT gather + softmax + bias + LayerNorm fused (one block per node) ----------------
__global__ void gat_gather_ln_kernel(const float* __restrict__ hg, const int* __restrict__ csr,
                                     const int* __restrict__ off, const float* __restrict__ as_,
                                     const float* __restrict__ ad_, const float* __restrict__ ab,
                                     const float* __restrict__ lg, const float* __restrict__ lb,
                                     float* __restrict__ outp) {
    int n = blockIdx.x, c = threadIdx.x, h = c >> 5;
    int beg = __ldg(&off[n]), end = __ldg(&off[n + 1]);
    float adn = __ldg(&ad_[n * HEADS + h]);
    float eself = lrelu(__ldg(&as_[n * HEADS + h]) + adn);

    float m = eself;
    for (int j = beg; j < end; j++) {
        int s = __ldg(&csr[j]);
        m = fmaxf(m, lrelu(__ldg(&as_[s * HEADS + h]) + adn));
    }
    float denom = expf(eself - m);
    float acc = hg[(size_t)n * HIDD + c] * denom;
    for (int j = beg; j < end; j++) {
        int s = __ldg(&csr[j]);
        float w = expf(lrelu(__ldg(&as_[s * HEADS + h]) + adn) - m);
        denom += w;
        acc += hg[(size_t)s * HIDD + c] * w;
    }
    float val = acc / denom + ab[c];

    // LayerNorm over the 256 channels of this node
    __shared__ float red[8];
    __shared__ float s_mu, s_rstd;
    float s = val;
#pragma unroll
    for (int o = 16; o; o >>= 1) s += __shfl_down_sync(0xffffffffu, s, o);
    if ((c & 31) == 0) red[c >> 5] = s;
    __syncthreads();
    if (c == 0) {
        float t = 0.f;
#pragma unroll
        for (int i = 0; i < 8; i++) t += red[i];
        s_mu = t * (1.0f / HIDD);
    }
    __syncthreads();
    float dv = val - s_mu;
    float q = dv * dv;
#pragma unroll
    for (int o = 16; o; o >>= 1) q += __shfl_down_sync(0xffffffffu, q, o);
    if ((c & 31) == 0) red[c >> 5] = q;
    __syncthreads();
    if (c == 0) {
        float t = 0.f;
#pragma unroll
        for (int i = 0; i < 8; i++) t += red[i];
        s_rstd = rsqrtf(t * (1.0f / HIDD) + LN_EPS);
    }
    __syncthreads();
    outp[(size_t)n * HIDD + c] = dv * s_rstd * lg[c] + lb[c];
}

// ---------------- fusion tail ----------------
__global__ void tanh_bias_kernel(float* __restrict__ t, const float* __restrict__ b) {
    int idx = blockIdx.x * 256 + threadIdx.x;
    int c = idx & (HIDD - 1);
    t[idx] = tanhf(t[idx] + b[c]);
}

__global__ void fuse_logits_kernel(const float* __restrict__ t, const float* __restrict__ W2,
                                   const float* __restrict__ b2, float* __restrict__ w) {
    int gw = (blockIdx.x * blockDim.x + threadIdx.x) >> 5;
    int lane = threadIdx.x & 31;
    if (gw >= NN) return;
    const float* row = t + (size_t)gw * HIDD;
    float a0 = 0.f, a1 = 0.f, a2 = 0.f, a3 = 0.f;
    for (int c = lane; c < HIDD; c += 32) {
        float tv = row[c];
        a0 += tv * W2[c * 4 + 0];
        a1 += tv * W2[c * 4 + 1];
        a2 += tv * W2[c * 4 + 2];
        a3 += tv * W2[c * 4 + 3];
    }
#pragma unroll
    for (int o = 16; o; o >>= 1) {
        a0 += __shfl_down_sync(0xffffffffu, a0, o);
        a1 += __shfl_down_sync(0xffffffffu, a1, o);
        a2 += __shfl_down_sync(0xffffffffu, a2, o);
        a3 += __shfl_down_sync(0xffffffffu, a3, o);
    }
    if (lane == 0) {
        float l0 = a0 + b2[0], l1 = a1 + b2[1], l2 = a2 + b2[2], l3 = a3 + b2[3];
        float mx = fmaxf(fmaxf(l0, l1), fmaxf(l2, l3));
        float e0 = expf(l0 - mx), e1 = expf(l1 - mx), e2 = expf(l2 - mx), e3 = expf(l3 - mx);
        float inv = 1.0f / (e0 + e1 + e2 + e3);
        w[gw * 4 + 0] = e0 * inv;
        w[gw * 4 + 1] = e1 * inv;
        w[gw * 4 + 2] = e2 * inv;
        w[gw * 4 + 3] = e3 * inv;
    }
}

__global__ void combine_kernel(const float* __restrict__ w, float* __restrict__ out) {
    int idx = blockIdx.x * 256 + threadIdx.x;
    int n = idx >> 8;
    float acc = 0.f;
#pragma unroll
    for (int k = 0; k < KK; k++) acc += w[n * KK + k] * g_outs[(size_t)k * NN * HIDD + idx];
    out[idx] = acc;
}

// ---------------- host ----------------
extern "C" void kernel_launch(void* const* d_in, const int* in_sizes, int n_in,
                              void* d_out, int out_size) {
    const float *x, *style, *stress;
    const int* ei[KK];
    int base;
    if (in_sizes[1] == 2 * EDGES) {
        x = (const float*)d_in[0];
        for (int k = 0; k < KK; k++) ei[k] = (const int*)d_in[1 + k];
        style = (const float*)d_in[5];
        stress = (const float*)d_in[6];
        base = 7;
    } else {
        x = (const float*)d_in[0];
        style = (const float*)d_in[1];
        stress = (const float*)d_in[2];
        for (int k = 0; k < KK; k++) ei[k] = (const int*)d_in[3 + k];
        base = 7;
    }
    const float* gW0 = (const float*)d_in[base + 0];
    const float* gb0 = (const float*)d_in[base + 1];
    const float* gW1 = (const float*)d_in[base + 2];
    const float* gb1 = (const float*)d_in[base + 3];
    const float* gW2 = (const float*)d_in[base + 4];
    const float* gb2 = (const float*)d_in[base + 5];
    const float* aW  = (const float*)d_in[base + 6];
    const float* aas = (const float*)d_in[base + 7];
    const float* aad = (const float*)d_in[base + 8];
    const float* ab  = (const float*)d_in[base + 9];
    const float* lg  = (const float*)d_in[base + 10];
    const float* lb  = (const float*)d_in[base + 11];
    const float* fW1 = (const float*)d_in[base + 12];
    const float* fb1 = (const float*)d_in[base + 13];
    const float* fW2 = (const float*)d_in[base + 14];
    const float* fb2 = (const float*)d_in[base + 15];

    float *h1, *h2, *h3, *outs, *dinv, *as_, *ad_, *wbuf;
    int *counts, *off, *cursor, *bsum, *csr;
    __nv_bfloat16* bsw;
    cudaGetSymbolAddress((void**)&h1, g_h1);
    cudaGetSymbolAddress((void**)&h2, g_h2);
    cudaGetSymbolAddress((void**)&h3, g_h3);
    cudaGetSymbolAddress((void**)&outs, g_outs);
    cudaGetSymbolAddress((void**)&dinv, g_dinv);
    cudaGetSymbolAddress((void**)&as_, g_as);
    cudaGetSymbolAddress((void**)&ad_, g_ad);
    cudaGetSymbolAddress((void**)&wbuf, g_w);
    cudaGetSymbolAddress((void**)&counts, g_counts);
    cudaGetSymbolAddress((void**)&off, g_off);
    cudaGetSymbolAddress((void**)&cursor, g_cursor);
    cudaGetSymbolAddress((void**)&bsum, g_bsum);
    cudaGetSymbolAddress((void**)&csr, g_csr);
    cudaGetSymbolAddress((void**)&bsw, g_bsplit);

    const size_t TOPO = 655360, OW1 = 262144, OW2 = 393216, OAW = 524288, OFUS = 2621440;
    dim3 ggrid(2, cdiv(NN, 128));

    // #1: all weight splits in one launch
    bsplit_all_kernel<<<dim3(512, 17), 256>>>(gW0, gW1, gW2, aW, fW1, bsw);
    // #2: zero all topo histograms
    zero_int_kernel<<<cdiv(KK * NN, 256), 256>>>(counts, KK * NN);

    for (int k = 0; k < KK; k++) {
        const int* src = ei[k];
        const int* dst = ei[k] + EDGES;
        const __nv_bfloat16* tb = bsw + (size_t)k * TOPO;
        int* cnt = counts + k * NN;

        // CSR build: hist -> scanA -> scanC(dinv) ; edge fill after first GEMM
        hist_kernel<<<cdiv(EDGES, 256), 256>>>(dst, cnt);
        scanA_kernel<<<SCAN_BLOCKS, 1024>>>(cnt, off, bsum);
        scanC_kernel<<<SCAN_BLOCKS, 1024>>>(cnt, off, cursor, bsum, dinv);

        // GCN L0: h1 = x@W0; h2 = h1*dinv^2 + b   (launch #6 on first iter -> ncu target)
        gemm_tc_kernel<<<ggrid, 256>>>(x, x + 256, IN_DIM, tb,
                                       h1, NN, IN_DIM, 0, h2, dinv, gb0 + k * HIDD);
        fillcsr_kernel<<<cdiv(EDGES, 256), 256>>>(src, dst, cursor, csr);
        gcn_gather_kernel<<<NN / 4, 256>>>(h1, csr, off, dinv, h2);

        // GCN L1
        gemm_tc_kernel<<<ggrid, 256>>>(h2, h2, HIDD, tb + OW1,
                                       h1, NN, HIDD, 1, h3, dinv, gb1 + k * HIDD);
        gcn_gather_kernel<<<NN / 4, 256>>>(h1, csr, off, dinv, h3);

        // GCN L2
        gemm_tc_kernel<<<ggrid, 256>>>(h3, h3, HIDD, tb + OW2,
                                       h1, NN, HIDD, 1, h2, dinv, gb2 + k * HIDD);
        gcn_gather_kernel<<<NN / 4, 256>>>(h1, csr, off, dinv, h2);

        // GAT + fused LN -> outs[k]
        gemm_tc_kernel<<<ggrid, 256>>>(h2, h2, HIDD, tb + OAW,
                                       h1, NN, HIDD, 1, nullptr, nullptr, nullptr);
        gat_asad_kernel<<<NN, 256>>>(h1, aas + k * HEADS * HC, aad + k * HEADS * HC, as_, ad_);
        gat_gather_ln_kernel<<<NN, 256>>>(h1, csr, off, as_, ad_, ab + k * HIDD,
                                          lg + k * HIDD, lb + k * HIDD,
                                          outs + (size_t)k * NN * HIDD);
    }

    // fusion
    gemm_tc_kernel<<<ggrid, 256>>>(style, stress, HIDD, bsw + OFUS,
                                   h1, NN, 2 * HIDD, 0, nullptr, nullptr, nullptr);
    tanh_bias_kernel<<<NN, 256>>>(h1, fb1);
    fuse_logits_kernel<<<cdiv(NN * 32, 256), 256>>>(h1, fW2, fb2, wbuf);
    combine_kernel<<<NN, 256>>>(wbuf, (float*)d_out);
}